// round 7
// baseline (speedup 1.0000x reference)
#include <cuda_runtime.h>
#include <cuda_bf16.h>
#include <cstdint>

#define NB_B 4096
#define ND 16
#define NM 4
#define NR 2048
#define NC 10
#define NDP1 17
#define MU 8.5f

typedef unsigned long long ull;

// cons planes, mean-centered bf16x2, laid out per rule-PAIR for LDG.128:
//   g_consA[q] = {p0/even, p0/odd, p1/even, p1/odd}
//   g_consB[q] = {p2/even, p2/odd, p3/even, p3/odd}
//   g_consC[q] = {p4/even, p4/odd}
__device__ uint4    g_consA[NR / 2];
__device__ uint4    g_consB[NR / 2];
__device__ uint2    g_consC[NR / 2];
__device__ unsigned g_rpack[NR];                        // 16 dims x 2 bits
__device__ float    g_norm_scratch[(size_t)NB_B * NR];  // fallback only

__device__ __forceinline__ unsigned spread16(unsigned v) {
    v &= 0xFFFFu;
    v = (v | (v << 8)) & 0x00FF00FFu;
    v = (v | (v << 4)) & 0x0F0F0F0Fu;
    v = (v | (v << 2)) & 0x33333333u;
    v = (v | (v << 1)) & 0x55555555u;
    return v;
}

__device__ __forceinline__ ull pack2(float x, float y) {
    ull r;
    asm("mov.b64 %0, {%1, %2};" : "=l"(r) : "f"(x), "f"(y));
    return r;
}
__device__ __forceinline__ void unpack2(float& x, float& y, ull v) {
    asm("mov.b64 {%0, %1}, %2;" : "=f"(x), "=f"(y) : "l"(v));
}
__device__ __forceinline__ void ffma2(ull& d, ull a, ull b) {
    asm("fma.rn.f32x2 %0, %1, %2, %0;" : "+l"(d) : "l"(a), "l"(b));
}
__device__ __forceinline__ ull fmul2(ull a, ull b) {
    ull r;
    asm("mul.rn.f32x2 %0, %1, %2;" : "=l"(r) : "l"(a), "l"(b));
    return r;
}

// ---------------------------------------------------------------------------
// K0: warp per rule. Shuffle-tree reduces cons[r,:,c]; lane 0 writes 5
// mean-centered bf16x2 words (pair-interleaved) + the ballot-packed indices.
// ---------------------------------------------------------------------------
__global__ __launch_bounds__(256) void prep_kernel(
    const float* __restrict__ cons, const int* __restrict__ rules) {
    const int gw   = (blockIdx.x * 256 + threadIdx.x) >> 5;  // rule id
    const int lane = threadIdx.x & 31;
    if (gw >= NR) return;

    float s[NC];
#pragma unroll
    for (int c = 0; c < NC; ++c) s[c] = 0.f;
    if (lane < NDP1) {
        const float* row = cons + (size_t)gw * NDP1 * NC + lane * NC;
#pragma unroll
        for (int c = 0; c < NC; ++c) s[c] = row[c];
    }
#pragma unroll
    for (int off = 16; off > 0; off >>= 1)
#pragma unroll
        for (int c = 0; c < NC; ++c)
            s[c] += __shfl_xor_sync(0xffffffffu, s[c], off);

    int v = (lane < ND) ? rules[gw * ND + lane] : 0;
    unsigned b0 = __ballot_sync(0xffffffffu, v & 1);
    unsigned b1 = __ballot_sync(0xffffffffu, (v >> 1) & 1);

    if (lane == 0) {
        const int q = gw >> 1, r1 = gw & 1;
        unsigned wbits[5];
#pragma unroll
        for (int p = 0; p < 5; ++p) {
            __nv_bfloat162 h =
                __floats2bfloat162_rn(s[2 * p] - MU, s[2 * p + 1] - MU);
            wbits[p] = *(unsigned*)&h;
        }
        ((unsigned*)g_consA)[q * 4 + 0 + r1] = wbits[0];
        ((unsigned*)g_consA)[q * 4 + 2 + r1] = wbits[1];
        ((unsigned*)g_consB)[q * 4 + 0 + r1] = wbits[2];
        ((unsigned*)g_consB)[q * 4 + 2 + r1] = wbits[3];
        ((unsigned*)g_consC)[q * 2 + r1]     = wbits[4];
        g_rpack[gw] = spread16(b0) | (spread16(b1) << 1);
    }
}

// ---------------------------------------------------------------------------
// K1 (fused): block = 256 thr = 8 warps = ONE batch-pair; 4 k-iters/warp.
// Pass 1: f (unnormalized) + sums + GEMV accumulate (packed plane-pair accs,
// accumulators die before pass 2 -> low peak regs). Pass 2: fn = f*inv, STG.
// ---------------------------------------------------------------------------
__global__ __launch_bounds__(256, 3) void fused_kernel(
    const float* __restrict__ x,
    const float* __restrict__ centers,
    const float* __restrict__ widths,
    float* __restrict__ norm_out,
    float* __restrict__ xext_out,
    float* __restrict__ out,
    int write_xext) {
    __shared__ float  s_e[2][64];
    __shared__ float2 s_tab[8][16];      // [table][idx] = (eA, eB)
    __shared__ float  s_sum[8][2];
    __shared__ float  s_acc[8][2][NC];
    __shared__ float  s_sx[2];

    const int tid  = threadIdx.x;
    const int w    = tid >> 5;
    const int lane = tid & 31;
    const int bA   = blockIdx.x * 2;
    const int bB   = bA + 1;

    // setup: warps 0,1 build per-batch tables (warp h -> component h)
    if (w < 2) {
        const int b = bA + w;
        float xv = (lane < ND) ? x[b * ND + lane] : 0.f;
        float sx = xv;
#pragma unroll
        for (int off = 16; off > 0; off >>= 1)
            sx += __shfl_xor_sync(0xffffffffu, sx, off);
        sx += 1.f;
        if (lane == 0) s_sx[w] = sx;
        if (write_xext) {
            if (lane < ND) xext_out[b * NDP1 + lane] = xv;
            if (lane == ND) xext_out[b * NDP1 + ND] = 1.f;
        }
#pragma unroll
        for (int k = lane; k < 64; k += 32) {
            int d = k >> 2, m = k & 3;
            float c  = centers[d * NM + m];
            float wd = widths[d * NM + m];
            float xd = __shfl_sync(0xffffffffu, xv, d);
            float dx = xd - c;
            s_e[w][k] = -(dx * dx) / (2.f * wd * wd);
        }
        __syncwarp();
#pragma unroll
        for (int k = lane; k < 128; k += 32) {
            int t = k >> 4, i = k & 15;
            float v = s_e[w][(2 * t) * 4 + (i & 3)] +
                      s_e[w][(2 * t + 1) * 4 + (i >> 2)];
            if (w == 0) s_tab[t][i].x = v;
            else        s_tab[t][i].y = v;
        }
    }
    __syncthreads();

    const uint2* __restrict__ rp = (const uint2*)g_rpack;

    // ---- pass 1: f, sums, and unnormalized GEMV ----
    ull  fpA[4], fpB[4];
    ull  accA[5], accB[5];               // packed (c=2p, c=2p+1)
    float sumA = 0.f, sumB = 0.f;
#pragma unroll
    for (int p = 0; p < 5; ++p) { accA[p] = 0ull; accB[p] = 0ull; }

#pragma unroll
    for (int k = 0; k < 4; ++k) {
        const int q = (w * 4 + k) * 32 + lane;    // rule-pair index
        uint2 pp = rp[q];
        float2 v0 = s_tab[0][pp.x & 15];
        float2 v1 = s_tab[0][pp.y & 15];
        float s0A = v0.x, s0B = v0.y, s1A = v1.x, s1B = v1.y;
#pragma unroll
        for (int t = 1; t < 8; ++t) {
            float2 a = s_tab[t][(pp.x >> (4 * t)) & 15];
            float2 b2 = s_tab[t][(pp.y >> (4 * t)) & 15];
            s0A += a.x;  s0B += a.y;
            s1A += b2.x; s1B += b2.y;
        }
        float f0A = __expf(s0A), f1A = __expf(s1A);
        float f0B = __expf(s0B), f1B = __expf(s1B);
        sumA += f0A + f1A;
        sumB += f0B + f1B;
        fpA[k] = pack2(f0A, f1A);
        fpB[k] = pack2(f0B, f1B);

        uint4 cA = g_consA[q];
        uint4 cB = g_consB[q];
        uint2 cC = g_consC[q];
        const unsigned we[5] = {cA.x, cA.z, cB.x, cB.z, cC.x};
        const unsigned wo[5] = {cA.y, cA.w, cB.y, cB.w, cC.y};
        const ull f0A2 = pack2(f0A, f0A), f1A2 = pack2(f1A, f1A);
        const ull f0B2 = pack2(f0B, f0B), f1B2 = pack2(f1B, f1B);
#pragma unroll
        for (int p = 0; p < 5; ++p) {
            ull ce = pack2(__uint_as_float(we[p] << 16),
                           __uint_as_float(we[p] & 0xffff0000u));
            ull co = pack2(__uint_as_float(wo[p] << 16),
                           __uint_as_float(wo[p] & 0xffff0000u));
            ffma2(accA[p], f0A2, ce);
            ffma2(accA[p], f1A2, co);
            ffma2(accB[p], f0B2, ce);
            ffma2(accB[p], f1B2, co);
        }
    }

    // reduce accumulators now (frees them before pass 2)
    float rA[NC], rB[NC];
#pragma unroll
    for (int p = 0; p < 5; ++p) {
        unpack2(rA[2 * p], rA[2 * p + 1], accA[p]);
        unpack2(rB[2 * p], rB[2 * p + 1], accB[p]);
    }
#pragma unroll
    for (int off = 16; off > 0; off >>= 1) {
        sumA += __shfl_xor_sync(0xffffffffu, sumA, off);
        sumB += __shfl_xor_sync(0xffffffffu, sumB, off);
#pragma unroll
        for (int c = 0; c < NC; ++c) {
            rA[c] += __shfl_xor_sync(0xffffffffu, rA[c], off);
            rB[c] += __shfl_xor_sync(0xffffffffu, rB[c], off);
        }
    }
    if (lane == 0) {
        s_sum[w][0] = sumA;
        s_sum[w][1] = sumB;
#pragma unroll
        for (int c = 0; c < NC; ++c) {
            s_acc[w][0][c] = rA[c];
            s_acc[w][1][c] = rB[c];
        }
    }
    __syncthreads();

    float totA = 0.f, totB = 0.f;
#pragma unroll
    for (int i = 0; i < 8; ++i) { totA += s_sum[i][0]; totB += s_sum[i][1]; }
    const float invA = 1.f / (totA + 1e-9f);
    const float invB = 1.f / (totB + 1e-9f);
    const ull invA2 = pack2(invA, invA);
    const ull invB2 = pack2(invB, invB);

    // ---- pass 2: normalized writes ----
    ull* npA = (ull*)(norm_out + (size_t)bA * NR);
    ull* npB = (ull*)(norm_out + (size_t)bB * NR);
#pragma unroll
    for (int k = 0; k < 4; ++k) {
        const int q = (w * 4 + k) * 32 + lane;
        npA[q] = fmul2(fpA[k], invA2);
        npB[q] = fmul2(fpB[k], invB2);
    }

    // ---- output ----
    if (tid < 20) {
        const int h = tid / 10, c = tid % 10;
        float a = 0.f;
#pragma unroll
        for (int i = 0; i < 8; ++i) a += s_acc[i][h][c];
        const float tot = h ? totB : totA;
        const float inv = h ? invB : invA;
        out[(size_t)(bA + h) * NC + c] = (a + MU * tot) * inv * s_sx[h];
    }
}

// ---------------------------------------------------------------------------
extern "C" void kernel_launch(void* const* d_in, const int* in_sizes, int n_in,
                              void* d_out, int out_size) {
    const float* x       = (const float*)d_in[0];
    const float* centers = (const float*)d_in[1];
    const float* widths  = (const float*)d_in[2];
    const float* cons    = (const float*)d_in[3];
    const int*   rules   = (const int*)d_in[4];
    float* out = (float*)d_out;

    const long long TOTAL = (long long)NB_B * NC + (long long)NB_B * NR +
                            (long long)NB_B * NDP1;

    float* out_p = out;
    float* norm_p;
    float* xext_p = out;
    int write_xext = 0;

    if ((long long)out_size == TOTAL) {
        norm_p = out + (size_t)NB_B * NC;
        xext_p = out + (size_t)NB_B * NC + (size_t)NB_B * NR;
        write_xext = 1;
    } else {
        void* sp = nullptr;
        cudaGetSymbolAddress(&sp, g_norm_scratch);
        norm_p = (float*)sp;
    }

    prep_kernel<<<NR / 8, 256>>>(cons, rules);
    fused_kernel<<<NB_B / 2, 256>>>(x, centers, widths, norm_p,
                                    xext_p, out_p, write_xext);
}